// round 2
// baseline (speedup 1.0000x reference)
#include <cuda_runtime.h>

#define M_MATCH 5000
#define TOT     10000      // 2*M
#define CF      128
#define CC      256
#define WW      25
#define LCELLS  4800
#define HFD     240
#define WFD     320

typedef unsigned long long ull;

// scratch
__device__ float g_t[TOT * CF];     // t[m][o] = C[m] @ Wc + bc   (5.12 MB)
__device__ float g_Wc[CC * CF];     // fused (W2 @ Wd)^T           (128 KB)
__device__ float g_bc[CF];

// packed fp32x2 FMA: acc = a*b + acc (elementwise on 2 floats)
#define FMA2(acc, a, b) asm("fma.rn.f32x2 %0, %1, %2, %0;" : "+l"(acc) : "l"(a), "l"(b))

// ---------------------------------------------------------------------------
// Kernel 0: Wc[c][o] = sum_j Wd[j][c] * W2[o][j],  W2 = merge_w[:,128:]
//           bc[o]    = sum_j W2[o][j] * bd[j] + bm[o]
// 16 blocks x 256 threads; W2 transposed in smem (pitch 129 -> conflict-free).
// ---------------------------------------------------------------------------
__global__ void __launch_bounds__(256)
wc_kernel(const float* __restrict__ Wd, const float* __restrict__ bd,
          const float* __restrict__ Wm, const float* __restrict__ bm)
{
    extern __shared__ float W2sT[];  // [128 j][129]
    const int tid = threadIdx.x;
    for (int idx = tid; idx < 128 * 128; idx += 256) {
        int o = idx >> 7, j = idx & 127;
        W2sT[j * 129 + o] = Wm[o * 256 + 128 + j];
    }
    __syncthreads();

    const int o = tid & 127, cs = tid >> 7;
    for (int ci = 0; ci < 8; ci++) {
        int c = blockIdx.x * 16 + cs * 8 + ci;
        float acc = 0.f;
        #pragma unroll 4
        for (int j = 0; j < 128; j++)
            acc += __ldg(&Wd[j * 256 + c]) * W2sT[j * 129 + o];
        g_Wc[c * 128 + o] = acc;
    }
    if (blockIdx.x == 0 && tid < 128) {
        float acc = bm[tid];
        for (int j = 0; j < 128; j++)
            acc += W2sT[j * 129 + tid] * bd[j];
        g_bc[tid] = acc;
    }
}

// ---------------------------------------------------------------------------
// Kernel 1: t[10000,128] = gather(feat_c)[10000,256] @ Wc + bc
// 64-match tiles (157 blocks), 256 threads, 4x8 FFMA2 microtile, k-chunks 64.
// ---------------------------------------------------------------------------
__global__ void __launch_bounds__(256, 1)
proj_kernel(const float* __restrict__ feat_c0, const float* __restrict__ feat_c1,
            const int* __restrict__ b_ids, const int* __restrict__ i_ids,
            const int* __restrict__ j_ids)
{
    extern __shared__ char sraw[];
    float2* A2  = (float2*)sraw;                                 // [64][64] dup  32 KB
    float*  Wcs = (float*)(sraw + 64 * 64 * 8);                  // [64][128]     32 KB
    const float** srow = (const float**)(sraw + 64*64*8 + 64*128*4);  // 64 ptrs

    const int tid  = threadIdx.x;
    const int tile = blockIdx.x;
    const int og = tid & 15, rg = tid >> 4;     // 16 o-groups x 16 r-groups
    const int o0 = og * 8, r0 = rg * 4;

    if (tid < 64) {
        int m = tile * 64 + tid;
        const float* p = nullptr;
        if (m < TOT) {
            int mm = (m < M_MATCH) ? m : m - M_MATCH;
            int b  = b_ids[mm];
            int l  = (m < M_MATCH) ? i_ids[mm] : j_ids[mm];
            p = ((m < M_MATCH) ? feat_c0 : feat_c1) + ((size_t)b * LCELLS + l) * CC;
        }
        srow[tid] = p;
    }

    ull acc[4][4];
    {
        ulonglong2 b0 = *(const ulonglong2*)&g_bc[o0];
        ulonglong2 b1 = *(const ulonglong2*)&g_bc[o0 + 4];
        #pragma unroll
        for (int j = 0; j < 4; j++) {
            acc[j][0] = b0.x; acc[j][1] = b0.y; acc[j][2] = b1.x; acc[j][3] = b1.y;
        }
    }
    __syncthreads();

    for (int kc = 0; kc < 256; kc += 64) {
        for (int idx = tid; idx < 64 * 64; idx += 256) {
            int r = idx >> 6, k = idx & 63;
            const float* p = srow[r];
            float v = p ? __ldg(p + kc + k) : 0.f;
            A2[idx] = make_float2(v, v);
        }
        for (int idx = tid; idx < 64 * 128; idx += 256)
            Wcs[idx] = g_Wc[(size_t)(kc + (idx >> 7)) * 128 + (idx & 127)];
        __syncthreads();

        #pragma unroll 2
        for (int c = 0; c < 64; c++) {
            ulonglong2 wa = *(const ulonglong2*)&Wcs[c * 128 + o0];
            ulonglong2 wb = *(const ulonglong2*)&Wcs[c * 128 + o0 + 4];
            #pragma unroll
            for (int j = 0; j < 4; j++) {
                ull fv = *(const ull*)&A2[(r0 + j) * 64 + c];
                FMA2(acc[j][0], fv, wa.x);
                FMA2(acc[j][1], fv, wa.y);
                FMA2(acc[j][2], fv, wb.x);
                FMA2(acc[j][3], fv, wb.y);
            }
        }
        __syncthreads();
    }

    #pragma unroll
    for (int j = 0; j < 4; j++) {
        int m = tile * 64 + r0 + j;
        if (m < TOT) {
            float* dst = &g_t[(size_t)m * CF + o0];
            *(ulonglong2*)dst       = make_ulonglong2(acc[j][0], acc[j][1]);
            *(ulonglong2*)(dst + 4) = make_ulonglong2(acc[j][2], acc[j][3]);
        }
    }
}

// ---------------------------------------------------------------------------
// Kernel 2: fine gather + merge GEMM.
// 5 matches per tile -> 125 rows packed into a 128x128 output tile.
// out[tile-row r, o] = sum_c f[r][c] * W1T[c][o] + t[m(r)][o]
// 8x8 microtile as FFMA2 (8 rows x 4 o-pairs), f duplicated {v,v} in smem.
// ---------------------------------------------------------------------------
__global__ void __launch_bounds__(256, 1)
fine_kernel(const float* __restrict__ feat_f0, const float* __restrict__ feat_f1,
            const int* __restrict__ b_ids, const int* __restrict__ i_ids,
            const int* __restrict__ j_ids,
            const float* __restrict__ Wm, float* __restrict__ out)
{
    extern __shared__ char sraw[];
    float*  W1T  = (float*)sraw;                          // [128 c][128 o] 64 KB
    float2* fsm2 = (float2*)(sraw + 65536);               // [128][128] dup (125 used) 128 KB
    int*    sl   = (int*)(sraw + 65536 + 131072);         // [5] cell ids
    ull*    sfb  = (ull*)(sraw + 65536 + 131072 + 24);    // [5] feature base ptrs

    const int tid = threadIdx.x;
    const int og = tid & 15, rg = tid >> 4;
    const int o0 = og * 8, r0 = rg * 8;

    for (int idx = tid; idx < 128 * 128; idx += 256) {
        int o = idx >> 7, c = idx & 127;
        W1T[c * 128 + o] = Wm[o * 256 + c];               // W1 = merge_w[:, :128]
    }

    for (int tile = blockIdx.x; tile < 2000; tile += gridDim.x) {
        if (tid < 5) {
            int m  = tile * 5 + tid;
            int mm = (m < M_MATCH) ? m : m - M_MATCH;
            int b  = b_ids[mm];
            sl[tid] = (m < M_MATCH) ? i_ids[mm] : j_ids[mm];
            const float* fb = ((m < M_MATCH) ? feat_f0 : feat_f1)
                            + (size_t)b * (CF * HFD * WFD);
            sfb[tid] = (ull)fb;
        }
        __syncthreads();

        // gather 125 rows x 128 c, duplicated for f32x2
        for (int e = tid; e < 16000; e += 256) {
            int r  = e >> 7;
            int mi = r / 25;                               // 0..4
            unsigned local = (unsigned)(e - mi * 3200);    // w*128 + c
            unsigned flat  = (unsigned)sl[mi] * 3200u + local;
            unsigned ch  = flat / 120000u;
            unsigned r1  = flat - ch * 120000u;
            unsigned k   = r1 / 4800u;
            unsigned pos = r1 - k * 4800u;
            int kh = (int)(k / 5u),  kw = (int)(k - 5u * (k / 5u));
            int oh = (int)(pos / 80u), ow = (int)(pos - 80u * (pos / 80u));
            int row = oh * 4 + kh - 2;
            int col = ow * 4 + kw - 2;
            float v = 0.f;
            if ((unsigned)row < (unsigned)HFD && (unsigned)col < (unsigned)WFD)
                v = __ldg((const float*)sfb[mi] + ((size_t)ch * HFD + row) * WFD + col);
            fsm2[e] = make_float2(v, v);
        }
        __syncthreads();

        // accumulator init from t (per-row match id; clamp rows 125..127)
        ull acc[8][4];
        #pragma unroll
        for (int j = 0; j < 8; j++) {
            int r = r0 + j;
            int m = tile * 5 + r / 25;
            if (m > TOT - 1) m = TOT - 1;
            const float* tp = &g_t[(size_t)m * CF + o0];
            ulonglong2 t0 = *(const ulonglong2*)tp;
            ulonglong2 t1 = *(const ulonglong2*)(tp + 4);
            acc[j][0] = t0.x; acc[j][1] = t0.y; acc[j][2] = t1.x; acc[j][3] = t1.y;
        }

        // 128x128x128 FFMA2 GEMM
        #pragma unroll 2
        for (int c = 0; c < 128; c++) {
            ulonglong2 wa = *(const ulonglong2*)&W1T[c * 128 + o0];
            ulonglong2 wb = *(const ulonglong2*)&W1T[c * 128 + o0 + 4];
            #pragma unroll
            for (int j = 0; j < 8; j++) {
                ull fv = *(const ull*)&fsm2[(r0 + j) * 128 + c];
                FMA2(acc[j][0], fv, wa.x);
                FMA2(acc[j][1], fv, wa.y);
                FMA2(acc[j][2], fv, wb.x);
                FMA2(acc[j][3], fv, wb.y);
            }
        }

        // store (rows 125..127 discarded)
        #pragma unroll
        for (int j = 0; j < 8; j++) {
            int r = r0 + j;
            if (r < 125) {
                int mi = r / 25;
                int w  = r - mi * 25;
                int m  = tile * 5 + mi;
                float* dst = &out[(size_t)m * 3200 + w * 128 + o0];
                *(ulonglong2*)dst       = make_ulonglong2(acc[j][0], acc[j][1]);
                *(ulonglong2*)(dst + 4) = make_ulonglong2(acc[j][2], acc[j][3]);
            }
        }
        __syncthreads();   // fsm2/sl reused next tile
    }
}

// ---------------------------------------------------------------------------
extern "C" void kernel_launch(void* const* d_in, const int* in_sizes, int n_in,
                              void* d_out, int out_size)
{
    (void)in_sizes; (void)n_in; (void)out_size;
    const float* feat_f0 = (const float*)d_in[0];
    const float* feat_f1 = (const float*)d_in[1];
    const float* feat_c0 = (const float*)d_in[2];
    const float* feat_c1 = (const float*)d_in[3];
    const int*   b_ids   = (const int*)d_in[4];
    const int*   i_ids   = (const int*)d_in[5];
    const int*   j_ids   = (const int*)d_in[6];
    const float* Wd      = (const float*)d_in[7];
    const float* bd      = (const float*)d_in[8];
    const float* Wm      = (const float*)d_in[9];
    const float* bm      = (const float*)d_in[10];
    float* out = (float*)d_out;

    const size_t smemW = 128 * 129 * sizeof(float);                      // 66048
    const size_t smemP = 64*64*8 + 64*128*4 + 64 * sizeof(float*);       // 66048
    const size_t smemF = 65536 + 131072 + 64;                            // 196672

    static int inited = 0;
    cudaFuncSetAttribute(wc_kernel,   cudaFuncAttributeMaxDynamicSharedMemorySize, (int)smemW);
    cudaFuncSetAttribute(proj_kernel, cudaFuncAttributeMaxDynamicSharedMemorySize, (int)smemP);
    cudaFuncSetAttribute(fine_kernel, cudaFuncAttributeMaxDynamicSharedMemorySize, (int)smemF);
    (void)inited;

    wc_kernel<<<16, 256, smemW>>>(Wd, bd, Wm, bm);
    proj_kernel<<<157, 256, smemP>>>(feat_c0, feat_c1, b_ids, i_ids, j_ids);
    fine_kernel<<<148, 256, smemF>>>(feat_f0, feat_f1, b_ids, i_ids, j_ids, Wm, out);
}

// round 3
// speedup vs baseline: 1.2224x; 1.2224x over previous
#include <cuda_runtime.h>

#define M_MATCH 5000
#define TOT     10000
#define CF      128
#define CC      256
#define WW      25
#define LCELLS  4800
#define HFD     240
#define WFD     320

typedef unsigned long long ull;

__device__ float g_t[TOT * CF];     // proj result
__device__ float g_Wc[CC * CF];     // fused (W2@Wd)^T, [c][o]
__device__ float g_bc[CF];          // fused bias

#define FMA2(acc, a, b) asm("fma.rn.f32x2 %0, %1, %2, %0;" : "+l"(acc) : "l"(a), "l"(b))

// ---------------------------------------------------------------------------
// Kernel 0: Wc[c][o] = sum_j Wd[j][c]*W2[o][j];  bc = W2@bd + bm
// 16 blocks x 256 thr; both operands staged in smem, per-thread ILP over 8 c.
// ---------------------------------------------------------------------------
__global__ void __launch_bounds__(256)
wc_kernel(const float* __restrict__ Wd, const float* __restrict__ bd,
          const float* __restrict__ Wm, const float* __restrict__ bm)
{
    extern __shared__ float sm[];
    float* w2T = sm;               // [j][129] -> 128*129
    float* wdT = sm + 128 * 129;   // [cc][132] -> 16*132
    const int tid = threadIdx.x;
    const int c0 = blockIdx.x * 16;

    for (int e = tid; e < 128 * 128; e += 256) {
        int o = e >> 7, j = e & 127;
        w2T[j * 129 + o] = Wm[o * 256 + 128 + j];
    }
    for (int e = tid; e < 2048; e += 256) {
        int j = e >> 4, cc = e & 15;
        wdT[cc * 132 + j] = Wd[j * 256 + c0 + cc];
    }
    __syncthreads();

    const int o = tid & 127;
    const int ccbase = (tid >> 7) * 8;
    #pragma unroll
    for (int q = 0; q < 8; q++) {
        int cc = ccbase + q;
        float acc = 0.f;
        #pragma unroll 4
        for (int j = 0; j < 128; j++)
            acc += wdT[cc * 132 + j] * w2T[j * 129 + o];
        g_Wc[(size_t)(c0 + cc) * 128 + o] = acc;
    }
    if (blockIdx.x == 0 && tid < 128) {
        float acc = bm[tid];
        for (int j = 0; j < 128; j++)
            acc += w2T[j * 129 + tid] * bd[j];
        g_bc[tid] = acc;
    }
}

// ---------------------------------------------------------------------------
// Kernel 1: t[10000,128] = gather(feat_c)[10000,256] @ Wc + bc
// 157 blocks x 256 thr, 64-match tile, 4 rows x 8 o per thread, k-chunks 64.
// ---------------------------------------------------------------------------
__global__ void __launch_bounds__(256, 2)
proj_kernel(const float* __restrict__ feat_c0, const float* __restrict__ feat_c1,
            const int* __restrict__ b_ids, const int* __restrict__ i_ids,
            const int* __restrict__ j_ids)
{
    extern __shared__ char sraw[];
    float* A   = (float*)sraw;                       // [64][64]  16 KB
    float* Wcs = (float*)(sraw + 16384);             // [64][128] 32 KB
    const float** srow = (const float**)(sraw + 16384 + 32768);

    const int tid = threadIdx.x;
    const int tile = blockIdx.x;
    const int og = tid & 15, rg = tid >> 4;
    const int o0 = og * 8;

    if (tid < 64) {
        int m = tile * 64 + tid;
        const float* p = nullptr;
        if (m < TOT) {
            int mm = (m < M_MATCH) ? m : m - M_MATCH;
            int b  = b_ids[mm];
            int l  = (m < M_MATCH) ? i_ids[mm] : j_ids[mm];
            p = ((m < M_MATCH) ? feat_c0 : feat_c1) + ((size_t)b * LCELLS + l) * CC;
        }
        srow[tid] = p;
    }

    float acc[4][8];
    {
        float4 bA = *(const float4*)&g_bc[o0];
        float4 bB = *(const float4*)&g_bc[o0 + 4];
        #pragma unroll
        for (int j = 0; j < 4; j++) {
            acc[j][0] = bA.x; acc[j][1] = bA.y; acc[j][2] = bA.z; acc[j][3] = bA.w;
            acc[j][4] = bB.x; acc[j][5] = bB.y; acc[j][6] = bB.z; acc[j][7] = bB.w;
        }
    }
    __syncthreads();

    for (int kc = 0; kc < 256; kc += 64) {
        for (int e = tid; e < 64 * 64; e += 256) {
            const float* p = srow[e >> 6];
            A[e] = p ? __ldg(p + kc + (e & 63)) : 0.f;
        }
        for (int e = tid; e < 64 * 128; e += 256)
            Wcs[e] = g_Wc[(size_t)(kc + (e >> 7)) * 128 + (e & 127)];
        __syncthreads();

        #pragma unroll 2
        for (int k = 0; k < 64; k += 4) {
            float4 fv[4];
            #pragma unroll
            for (int j = 0; j < 4; j++)
                fv[j] = *(const float4*)&A[(rg + 16 * j) * 64 + k];
            #define PSTEP(kk, COMP)                                            \
            {                                                                  \
                float4 wA = *(const float4*)&Wcs[(k + kk) * 128 + o0];         \
                float4 wB = *(const float4*)&Wcs[(k + kk) * 128 + o0 + 4];     \
                _Pragma("unroll")                                              \
                for (int j = 0; j < 4; j++) {                                  \
                    float a = fv[j].COMP;                                      \
                    acc[j][0] += a * wA.x; acc[j][1] += a * wA.y;              \
                    acc[j][2] += a * wA.z; acc[j][3] += a * wA.w;              \
                    acc[j][4] += a * wB.x; acc[j][5] += a * wB.y;              \
                    acc[j][6] += a * wB.z; acc[j][7] += a * wB.w;              \
                }                                                              \
            }
            PSTEP(0, x) PSTEP(1, y) PSTEP(2, z) PSTEP(3, w)
            #undef PSTEP
        }
        __syncthreads();
    }

    #pragma unroll
    for (int j = 0; j < 4; j++) {
        int m = tile * 64 + rg + 16 * j;
        if (m < TOT) {
            float* dst = &g_t[(size_t)m * CF + o0];
            *(float4*)dst       = make_float4(acc[j][0], acc[j][1], acc[j][2], acc[j][3]);
            *(float4*)(dst + 4) = make_float4(acc[j][4], acc[j][5], acc[j][6], acc[j][7]);
        }
    }
}

// ---------------------------------------------------------------------------
// Fine kernels: 5 matches/tile (125 rows of a 128x128x128 GEMM tile).
// Shared structure: 512 thr, og=tid&15 (o0=og*8), rg=tid>>4 (rows rg+32j).
// fineA: plain FFMA.   fineB: FFMA2 (fp32x2), duplicated activations.
// ---------------------------------------------------------------------------
__global__ void __launch_bounds__(512, 1)
fineA_kernel(const float* __restrict__ feat_f0, const float* __restrict__ feat_f1,
             const int* __restrict__ b_ids, const int* __restrict__ i_ids,
             const int* __restrict__ j_ids,
             const float* __restrict__ Wm, float* __restrict__ out,
             int tile0, int tile1)
{
    extern __shared__ char sraw[];
    float* W1T = (float*)sraw;                 // [c][o] 64 KB
    float* fsm = (float*)(sraw + 65536);       // [128][128] 64 KB
    int*   sl  = (int*)(sraw + 131072);
    ull*   sfb = (ull*)(sraw + 131072 + 32);

    const int tid = threadIdx.x;
    const int og = tid & 15, rg = tid >> 4;
    const int o0 = og * 8;

    for (int e = tid; e < 128 * 128; e += 512) {
        int o = e >> 7, c = e & 127;
        W1T[c * 128 + o] = Wm[o * 256 + c];
    }

    for (int tile = tile0 + blockIdx.x; tile < tile1; tile += gridDim.x) {
        if (tid < 5) {
            int m  = tile * 5 + tid;
            int mm = (m < M_MATCH) ? m : m - M_MATCH;
            int b  = b_ids[mm];
            sl[tid]  = (m < M_MATCH) ? i_ids[mm] : j_ids[mm];
            sfb[tid] = (ull)(((m < M_MATCH) ? feat_f0 : feat_f1)
                             + (size_t)b * (CF * HFD * WFD));
        }
        __syncthreads();

        for (int e = tid; e < 16000; e += 512) {
            int r  = e >> 7;
            int mi = r / 25;
            unsigned flat = (unsigned)sl[mi] * 3200u + (unsigned)(e - mi * 3200);
            unsigned ch  = flat / 120000u;
            unsigned r1  = flat - ch * 120000u;
            unsigned k   = r1 / 4800u;
            unsigned pos = r1 - k * 4800u;
            int row = (int)(pos / 80u) * 4 + (int)(k / 5u) - 2;
            int col = (int)(pos - 80u * (pos / 80u)) * 4 + (int)(k - 5u * (k / 5u)) - 2;
            float v = 0.f;
            if ((unsigned)row < (unsigned)HFD && (unsigned)col < (unsigned)WFD)
                v = __ldg((const float*)sfb[mi] + ((size_t)ch * HFD + row) * WFD + col);
            fsm[e] = v;
        }
        __syncthreads();

        float acc[4][8];
        #pragma unroll
        for (int j = 0; j < 4; j++) {
            int r = rg + 32 * j;
            int m = tile * 5 + r / 25;
            if (m > TOT - 1) m = TOT - 1;
            float4 tA = *(const float4*)&g_t[(size_t)m * CF + o0];
            float4 tB = *(const float4*)&g_t[(size_t)m * CF + o0 + 4];
            acc[j][0] = tA.x; acc[j][1] = tA.y; acc[j][2] = tA.z; acc[j][3] = tA.w;
            acc[j][4] = tB.x; acc[j][5] = tB.y; acc[j][6] = tB.z; acc[j][7] = tB.w;
        }

        #pragma unroll 2
        for (int c = 0; c < 128; c += 4) {
            float4 fv[4];
            #pragma unroll
            for (int j = 0; j < 4; j++)
                fv[j] = *(const float4*)&fsm[(rg + 32 * j) * 128 + c];
            #define FSTEP(kk, COMP)                                            \
            {                                                                  \
                float4 wA = *(const float4*)&W1T[(c + kk) * 128 + o0];         \
                float4 wB = *(const float4*)&W1T[(c + kk) * 128 + o0 + 4];     \
                _Pragma("unroll")                                              \
                for (int j = 0; j < 4; j++) {                                  \
                    float a = fv[j].COMP;                                      \
                    acc[j][0] += a * wA.x; acc[j][1] += a * wA.y;              \
                    acc[j][2] += a * wA.z; acc[j][3] += a * wA.w;              \
                    acc[j][4] += a * wB.x; acc[j][5] += a * wB.y;              \
                    acc[j][6] += a * wB.z; acc[j][7] += a * wB.w;              \
                }                                                              \
            }
            FSTEP(0, x) FSTEP(1, y) FSTEP(2, z) FSTEP(3, w)
            #undef FSTEP
        }

        #pragma unroll
        for (int j = 0; j < 4; j++) {
            int r = rg + 32 * j;
            if (r < 125) {
                int mi = r / 25;
                int w  = r - mi * 25;
                float* dst = &out[(size_t)(tile * 5 + mi) * 3200 + w * 128 + o0];
                *(float4*)dst       = make_float4(acc[j][0], acc[j][1], acc[j][2], acc[j][3]);
                *(float4*)(dst + 4) = make_float4(acc[j][4], acc[j][5], acc[j][6], acc[j][7]);
            }
        }
        __syncthreads();
    }
}

__global__ void __launch_bounds__(512, 1)
fineB_kernel(const float* __restrict__ feat_f0, const float* __restrict__ feat_f1,
             const int* __restrict__ b_ids, const int* __restrict__ i_ids,
             const int* __restrict__ j_ids,
             const float* __restrict__ Wm, float* __restrict__ out,
             int tile0, int tile1)
{
    extern __shared__ char sraw[];
    float*  W1T  = (float*)sraw;               // [c][o] 64 KB
    float2* fsm2 = (float2*)(sraw + 65536);    // [128][128] dup 128 KB
    int*    sl   = (int*)(sraw + 65536 + 131072);
    ull*    sfb  = (ull*)(sraw + 65536 + 131072 + 32);

    const int tid = threadIdx.x;
    const int og = tid & 15, rg = tid >> 4;
    const int o0 = og * 8;

    for (int e = tid; e < 128 * 128; e += 512) {
        int o = e >> 7, c = e & 127;
        W1T[c * 128 + o] = Wm[o * 256 + c];
    }

    for (int tile = tile0 + blockIdx.x; tile < tile1; tile += gridDim.x) {
        if (tid < 5) {
            int m  = tile * 5 + tid;
            int mm = (m < M_MATCH) ? m : m - M_MATCH;
            int b  = b_ids[mm];
            sl[tid]  = (m < M_MATCH) ? i_ids[mm] : j_ids[mm];
            sfb[tid] = (ull)(((m < M_MATCH) ? feat_f0 : feat_f1)
                             + (size_t)b * (CF * HFD * WFD));
        }
        __syncthreads();

        for (int e = tid; e < 16000; e += 512) {
            int r  = e >> 7;
            int mi = r / 25;
            unsigned flat = (unsigned)sl[mi] * 3200u + (unsigned)(e - mi * 3200);
            unsigned ch  = flat / 120000u;
            unsigned r1  = flat - ch * 120000u;
            unsigned k   = r1 / 4800u;
            unsigned pos = r1 - k * 4800u;
            int row = (int)(pos / 80u) * 4 + (int)(k / 5u) - 2;
            int col = (int)(pos - 80u * (pos / 80u)) * 4 + (int)(k - 5u * (k / 5u)) - 2;
            float v = 0.f;
            if ((unsigned)row < (unsigned)HFD && (unsigned)col < (unsigned)WFD)
                v = __ldg((const float*)sfb[mi] + ((size_t)ch * HFD + row) * WFD + col);
            fsm2[e] = make_float2(v, v);
        }
        __syncthreads();

        ull acc[4][4];
        #pragma unroll
        for (int j = 0; j < 4; j++) {
            int r = rg + 32 * j;
            int m = tile * 5 + r / 25;
            if (m > TOT - 1) m = TOT - 1;
            ulonglong2 tA = *(const ulonglong2*)&g_t[(size_t)m * CF + o0];
            ulonglong2 tB = *(const ulonglong2*)&g_t[(size_t)m * CF + o0 + 4];
            acc[j][0] = tA.x; acc[j][1] = tA.y; acc[j][2] = tB.x; acc[j][3] = tB.y;
        }

        #pragma unroll 2
        for (int c = 0; c < 128; c += 2) {
            ulonglong2 wa0 = *(const ulonglong2*)&W1T[c * 128 + o0];
            ulonglong2 wb0 = *(const ulonglong2*)&W1T[c * 128 + o0 + 4];
            ulonglong2 wa1 = *(const ulonglong2*)&W1T[(c + 1) * 128 + o0];
            ulonglong2 wb1 = *(const ulonglong2*)&W1T[(c + 1) * 128 + o0 + 4];
            #pragma unroll
            for (int j = 0; j < 4; j++) {
                ulonglong2 f = *(const ulonglong2*)&fsm2[(rg + 32 * j) * 128 + c];
                FMA2(acc[j][0], f.x, wa0.x);
                FMA2(acc[j][1], f.x, wa0.y);
                FMA2(acc[j][2], f.x, wb0.x);
                FMA2(acc[j][3], f.x, wb0.y);
                FMA2(acc[j][0], f.y, wa1.x);
                FMA2(acc[j][1], f.y, wa1.y);
                FMA2(acc[j][2], f.y, wb1.x);
                FMA2(acc[j][3], f.y, wb1.y);
            }
        }

        #pragma unroll
        for (int j = 0; j < 4; j++) {
            int r = rg + 32 * j;
            if (r < 125) {
                int mi = r / 25;
                int w  = r - mi * 25;
                float* dst = &out[(size_t)(tile * 5 + mi) * 3200 + w * 128 + o0];
                *(ulonglong2*)dst       = make_ulonglong2(acc[j][0], acc[j][1]);
                *(ulonglong2*)(dst + 4) = make_ulonglong2(acc[j][2], acc[j][3]);
            }
        }
        __syncthreads();
    }
}

// ---------------------------------------------------------------------------
extern "C" void kernel_launch(void* const* d_in, const int* in_sizes, int n_in,
                              void* d_out, int out_size)
{
    (void)in_sizes; (void)n_in; (void)out_size;
    const float* feat_f0 = (const float*)d_in[0];
    const float* feat_f1 = (const float*)d_in[1];
    const float* feat_c0 = (const float*)d_in[2];
    const float* feat_c1 = (const float*)d_in[3];
    const int*   b_ids   = (const int*)d_in[4];
    const int*   i_ids   = (const int*)d_in[5];
    const int*   j_ids   = (const int*)d_in[6];
    const float* Wd      = (const float*)d_in[7];
    const float* bd      = (const float*)d_in[8];
    const float* Wm      = (const float*)d_in[9];
    const float* bm      = (const float*)d_in[10];
    float* out = (float*)d_out;

    const size_t smemW = (128 * 129 + 16 * 132) * sizeof(float);
    const size_t smemP = 16384 + 32768 + 64 * sizeof(float*);
    const size_t smemA = 65536 + 65536 + 96;
    const size_t smemB = 65536 + 131072 + 96;

    cudaFuncSetAttribute(wc_kernel,    cudaFuncAttributeMaxDynamicSharedMemorySize, (int)smemW);
    cudaFuncSetAttribute(proj_kernel,  cudaFuncAttributeMaxDynamicSharedMemorySize, (int)smemP);
    cudaFuncSetAttribute(fineA_kernel, cudaFuncAttributeMaxDynamicSharedMemorySize, (int)smemA);
    cudaFuncSetAttribute(fineB_kernel, cudaFuncAttributeMaxDynamicSharedMemorySize, (int)smemB);

    wc_kernel<<<16, 256, smemW>>>(Wd, bd, Wm, bm);
    proj_kernel<<<157, 256, smemP>>>(feat_c0, feat_c1, b_ids, i_ids, j_ids);
    fineA_kernel<<<148, 512, smemA>>>(feat_f0, feat_f1, b_ids, i_ids, j_ids, Wm, out, 0, 1000);
    fineB_kernel<<<148, 512, smemB>>>(feat_f0, feat_f1, b_ids, i_ids, j_ids, Wm, out, 1000, 2000);
}

// round 5
// speedup vs baseline: 1.7391x; 1.4226x over previous
#include <cuda_runtime.h>
#include <cuda_bf16.h>
#include <cstdint>

#define M_MATCH 5000
#define TOT     10000
#define CF      128
#define CC      256
#define WW      25
#define LCELLS  4800
#define HFD     240
#define WFD     320

typedef unsigned long long ull;

__device__ float g_t[TOT * CF];     // proj result t[m][o]
__device__ float g_Wc[CC * CF];     // fused (W2@Wd)^T, [c][o]
__device__ float g_bc[CF];

__device__ __forceinline__ uint32_t smem_u32(const void* p) {
    uint32_t a;
    asm("{ .reg .u64 t; cvta.to.shared.u64 t, %1; cvt.u32.u64 %0, t; }" : "=r"(a) : "l"(p));
    return a;
}

#define LDSM_X4(r0, r1, r2, r3, addr)                                          \
    asm volatile("ldmatrix.sync.aligned.m8n8.x4.shared.b16 {%0,%1,%2,%3}, [%4];" \
        : "=r"(r0), "=r"(r1), "=r"(r2), "=r"(r3) : "r"(addr))

#define MMA16816(d, a0, a1, a2, a3, b0, b1)                                    \
    asm volatile("mma.sync.aligned.m16n8k16.row.col.f32.bf16.bf16.f32 "        \
        "{%0,%1,%2,%3}, {%4,%5,%6,%7}, {%8,%9}, {%0,%1,%2,%3};"                \
        : "+f"((d)[0]), "+f"((d)[1]), "+f"((d)[2]), "+f"((d)[3])               \
        : "r"(a0), "r"(a1), "r"(a2), "r"(a3), "r"(b0), "r"(b1))

// ---------------------------------------------------------------------------
// Kernel 0: Wc = (W2 @ Wd) transposed to [c][o];  bc = W2@bd + bm
// ---------------------------------------------------------------------------
__global__ void __launch_bounds__(256)
wc_kernel(const float* __restrict__ Wd, const float* __restrict__ bd,
          const float* __restrict__ Wm, const float* __restrict__ bm)
{
    extern __shared__ float sm[];
    float* w2T = sm;               // [j][129]
    float* wdT = sm + 128 * 129;   // [cc][132]
    const int tid = threadIdx.x;
    const int c0 = blockIdx.x * 16;

    for (int e = tid; e < 128 * 128; e += 256) {
        int o = e >> 7, j = e & 127;
        w2T[j * 129 + o] = Wm[o * 256 + 128 + j];
    }
    for (int e = tid; e < 2048; e += 256) {
        int j = e >> 4, cc = e & 15;
        wdT[cc * 132 + j] = Wd[j * 256 + c0 + cc];
    }
    __syncthreads();

    const int o = tid & 127;
    const int ccbase = (tid >> 7) * 8;
    #pragma unroll
    for (int q = 0; q < 8; q++) {
        int cc = ccbase + q;
        float acc = 0.f;
        #pragma unroll 4
        for (int j = 0; j < 128; j++)
            acc += wdT[cc * 132 + j] * w2T[j * 129 + o];
        g_Wc[(size_t)(c0 + cc) * 128 + o] = acc;
    }
    if (blockIdx.x == 0 && tid < 128) {
        float acc = bm[tid];
        for (int j = 0; j < 128; j++)
            acc += w2T[j * 129 + tid] * bd[j];
        g_bc[tid] = acc;
    }
}

// ---------------------------------------------------------------------------
// Kernel 1: t[10000,128] = gather(feat_c) @ Wc + bc
// ---------------------------------------------------------------------------
__global__ void __launch_bounds__(256, 2)
proj_kernel(const float* __restrict__ feat_c0, const float* __restrict__ feat_c1,
            const int* __restrict__ b_ids, const int* __restrict__ i_ids,
            const int* __restrict__ j_ids)
{
    extern __shared__ char sraw[];
    float* A   = (float*)sraw;                       // [64][64]
    float* Wcs = (float*)(sraw + 16384);             // [64][128]
    const float** srow = (const float**)(sraw + 16384 + 32768);

    const int tid = threadIdx.x;
    const int tile = blockIdx.x;
    const int og = tid & 15, rg = tid >> 4;
    const int o0 = og * 8;

    if (tid < 64) {
        int m = tile * 64 + tid;
        const float* p = nullptr;
        if (m < TOT) {
            int mm = (m < M_MATCH) ? m : m - M_MATCH;
            int b  = b_ids[mm];
            int l  = (m < M_MATCH) ? i_ids[mm] : j_ids[mm];
            p = ((m < M_MATCH) ? feat_c0 : feat_c1) + ((size_t)b * LCELLS + l) * CC;
        }
        srow[tid] = p;
    }

    float acc[4][8];
    {
        float4 bA = *(const float4*)&g_bc[o0];
        float4 bB = *(const float4*)&g_bc[o0 + 4];
        #pragma unroll
        for (int j = 0; j < 4; j++) {
            acc[j][0] = bA.x; acc[j][1] = bA.y; acc[j][2] = bA.z; acc[j][3] = bA.w;
            acc[j][4] = bB.x; acc[j][5] = bB.y; acc[j][6] = bB.z; acc[j][7] = bB.w;
        }
    }
    __syncthreads();

    for (int kc = 0; kc < 256; kc += 64) {
        for (int e = tid; e < 64 * 64; e += 256) {
            const float* p = srow[e >> 6];
            A[e] = p ? __ldg(p + kc + (e & 63)) : 0.f;
        }
        for (int e = tid; e < 64 * 128; e += 256)
            Wcs[e] = g_Wc[(size_t)(kc + (e >> 7)) * 128 + (e & 127)];
        __syncthreads();

        #pragma unroll 2
        for (int k = 0; k < 64; k += 4) {
            float4 fv[4];
            #pragma unroll
            for (int j = 0; j < 4; j++)
                fv[j] = *(const float4*)&A[(rg + 16 * j) * 64 + k];
            #define PSTEP(kk, COMP)                                            \
            {                                                                  \
                float4 wA = *(const float4*)&Wcs[(k + kk) * 128 + o0];         \
                float4 wB = *(const float4*)&Wcs[(k + kk) * 128 + o0 + 4];     \
                _Pragma("unroll")                                              \
                for (int j = 0; j < 4; j++) {                                  \
                    float a = fv[j].COMP;                                      \
                    acc[j][0] += a * wA.x; acc[j][1] += a * wA.y;              \
                    acc[j][2] += a * wA.z; acc[j][3] += a * wA.w;              \
                    acc[j][4] += a * wB.x; acc[j][5] += a * wB.y;              \
                    acc[j][6] += a * wB.z; acc[j][7] += a * wB.w;              \
                }                                                              \
            }
            PSTEP(0, x) PSTEP(1, y) PSTEP(2, z) PSTEP(3, w)
            #undef PSTEP
        }
        __syncthreads();
    }

    #pragma unroll
    for (int j = 0; j < 4; j++) {
        int m = tile * 64 + rg + 16 * j;
        if (m < TOT) {
            float* dst = &g_t[(size_t)m * CF + o0];
            *(float4*)dst       = make_float4(acc[j][0], acc[j][1], acc[j][2], acc[j][3]);
            *(float4*)(dst + 4) = make_float4(acc[j][4], acc[j][5], acc[j][6], acc[j][7]);
        }
    }
}

// ---------------------------------------------------------------------------
// Kernel 2: fine gather + HMMA (mma.sync bf16) merge GEMM, 3-term hi/lo split.
// Per tile: 5 matches -> 125 rows of a 128x128x128 GEMM.
// 8 warps: (w&3) -> 32-row group, (w>>2) -> 64-col group.
// ---------------------------------------------------------------------------
#define APITCH 136                    // bf16 elements per row (272 B)
#define ABYTES (128 * APITCH * 2)     // 34816

__global__ void __launch_bounds__(256)
fine_kernel(const float* __restrict__ feat_f0, const float* __restrict__ feat_f1,
            const int* __restrict__ b_ids, const int* __restrict__ i_ids,
            const int* __restrict__ j_ids,
            const float* __restrict__ Wm, float* __restrict__ out)
{
    extern __shared__ char sraw[];
    char* Ah = sraw;
    char* Al = sraw + ABYTES;
    char* Bh = sraw + 2 * ABYTES;
    char* Bl = sraw + 3 * ABYTES;
    float* t_s = (float*)(sraw + 4 * ABYTES);        // [5][128]
    int*   sl  = (int*)(sraw + 4 * ABYTES + 2560);
    ull*   sfb = (ull*)(sraw + 4 * ABYTES + 2592);

    const uint32_t sAh = smem_u32(Ah);
    const uint32_t sAl = smem_u32(Al);
    const uint32_t sBh = smem_u32(Bh);
    const uint32_t sBl = smem_u32(Bl);

    const int tid = threadIdx.x;
    const int wid = tid >> 5;
    const int lane = tid & 31;

    // B prep: W1 = merge_w[:, :128], hi/lo split, [o][c] rows at pitch APITCH
    for (int e2 = tid; e2 < 8192; e2 += 256) {
        int o = e2 >> 6;
        int c = (e2 & 63) * 2;
        float v0 = Wm[o * 256 + c];
        float v1 = Wm[o * 256 + c + 1];
        __nv_bfloat16 h0 = __float2bfloat16(v0);
        __nv_bfloat16 h1 = __float2bfloat16(v1);
        __nv_bfloat16 l0 = __float2bfloat16(v0 - __bfloat162float(h0));
        __nv_bfloat16 l1 = __float2bfloat16(v1 - __bfloat162float(h1));
        __nv_bfloat162 hp, lp; hp.x = h0; hp.y = h1; lp.x = l0; lp.y = l1;
        *(uint32_t*)(Bh + o * (APITCH * 2) + c * 2) = *(uint32_t*)&hp;
        *(uint32_t*)(Bl + o * (APITCH * 2) + c * 2) = *(uint32_t*)&lp;
    }

    const int mbase = (wid & 3) * 32;
    const int nbase = (wid >> 2) * 64;

    // per-lane ldmatrix address components (byte offsets, k=0)
    // A: row = mbase + i*16 + (lane&15), col-half = (lane>>4)*8
    const uint32_t aRow = (uint32_t)(mbase + (lane & 15));
    const uint32_t aColB = (uint32_t)((lane >> 4) * 16);       // bytes
    // B: row(n) = nbase + bb*16 + (lane&7) + (lane>>4)*8 ; col-half = ((lane>>3)&1)*8
    const uint32_t bRow = (uint32_t)(nbase + (lane & 7) + ((lane >> 4) << 3));
    const uint32_t bColB = (uint32_t)(((lane >> 3) & 1) * 16); // bytes

    __syncthreads();

    for (int tile = blockIdx.x; tile < 2000; tile += gridDim.x) {
        if (tid < 5) {
            int m  = tile * 5 + tid;
            int mm = (m < M_MATCH) ? m : m - M_MATCH;
            int b  = b_ids[mm];
            sl[tid]  = (m < M_MATCH) ? i_ids[mm] : j_ids[mm];
            sfb[tid] = (ull)(((m < M_MATCH) ? feat_f0 : feat_f1)
                             + (size_t)b * (CF * HFD * WFD));
        }
        __syncthreads();

        for (int e = tid; e < 640; e += 256)
            t_s[e] = g_t[(size_t)(tile * 5 + (e >> 7)) * CF + (e & 127)];

        // gather A (hi/lo) — rows 125..127 zeroed
        for (int e2 = tid; e2 < 8192; e2 += 256) {
            int r = e2 >> 6;
            int c = (e2 & 63) * 2;
            uint32_t hp = 0, lp = 0;
            if (r < 125) {
                int mi = r / 25;
                int w  = r - mi * 25;
                const float* fb = (const float*)sfb[mi];
                unsigned fl0 = (unsigned)sl[mi] * 3200u + (unsigned)(w * 128 + c);
                float v[2];
                #pragma unroll
                for (int q = 0; q < 2; q++) {
                    unsigned flat = fl0 + (unsigned)q;
                    unsigned ch  = flat / 120000u;
                    unsigned r1  = flat - ch * 120000u;
                    unsigned k   = r1 / 4800u;
                    unsigned pos = r1 - k * 4800u;
                    int row = (int)(pos / 80u) * 4 + (int)(k / 5u) - 2;
                    int col = (int)(pos - 80u * (pos / 80u)) * 4 + (int)(k - 5u * (k / 5u)) - 2;
                    float vv = 0.f;
                    if ((unsigned)row < (unsigned)HFD && (unsigned)col < (unsigned)WFD)
                        vv = __ldg(fb + ((size_t)ch * HFD + row) * WFD + col);
                    v[q] = vv;
                }
                __nv_bfloat16 h0 = __float2bfloat16(v[0]);
                __nv_bfloat16 h1 = __float2bfloat16(v[1]);
                __nv_bfloat16 l0 = __float2bfloat16(v[0] - __bfloat162float(h0));
                __nv_bfloat16 l1 = __float2bfloat16(v[1] - __bfloat162float(h1));
                __nv_bfloat162 hh, ll; hh.x = h0; hh.y = h1; ll.x = l0; ll.y = l1;
                hp = *(uint32_t*)&hh; lp = *(uint32_t*)&ll;
            }
            *(uint32_t*)(Ah + r * (APITCH * 2) + c * 2) = hp;
            *(uint32_t*)(Al + r * (APITCH * 2) + c * 2) = lp;
        }
        __syncthreads();

        float acc[2][8][4];
        #pragma unroll
        for (int i = 0; i < 2; i++)
            #pragma unroll
            for (int nb = 0; nb < 8; nb++) {
                acc[i][nb][0] = 0.f; acc[i][nb][1] = 0.f;
                acc[i][nb][2] = 0.f; acc[i][nb][3] = 0.f;
            }

        #pragma unroll 1
        for (int ks = 0; ks < 8; ks++) {
            const uint32_t kb = (uint32_t)(ks * 32);   // 16 bf16 = 32 bytes
            uint32_t a0_0, a0_1, a0_2, a0_3, a1_0, a1_1, a1_2, a1_3;
            uint32_t bfr[8][2];

            // term 1: Ah * Bh
            LDSM_X4(a0_0, a0_1, a0_2, a0_3, sAh + aRow * 272 + kb + aColB);
            LDSM_X4(a1_0, a1_1, a1_2, a1_3, sAh + (aRow + 16) * 272 + kb + aColB);
            #pragma unroll
            for (int bb = 0; bb < 4; bb++)
                LDSM_X4(bfr[2*bb][0], bfr[2*bb][1], bfr[2*bb+1][0], bfr[2*bb+1][1],
                        sBh + (bRow + bb * 16) * 272 + kb + bColB);
            #pragma unroll
            for (int nb = 0; nb < 8; nb++) {
                MMA16816(acc[0][nb], a0_0, a0_1, a0_2, a0_3, bfr[nb][0], bfr[nb][1]);
                MMA16816(acc[1][nb], a1_0, a1_1, a1_2, a1_3, bfr[nb][0], bfr[nb][1]);
            }
            // term 2: Ah * Bl  (A frags still live)
            #pragma unroll
            for (int bb = 0; bb < 4; bb++)
                LDSM_X4(bfr[2*bb][0], bfr[2*bb][1], bfr[2*bb+1][0], bfr[2*bb+1][1],
                        sBl + (bRow + bb * 16) * 272 + kb + bColB);
            #pragma unroll
            for (int nb = 0; nb < 8; nb++) {
                MMA16816(acc[0][nb], a0_0, a0_1, a0_2, a0_3, bfr[nb][0], bfr[nb][1]);
                MMA16816(acc[1][nb], a1_0, a1_1, a1_2, a1_3, bfr[nb][0], bfr[nb][1]);
            }
            // term 3: Al * Bh
            LDSM_X4(a0_0, a0_1, a0_2, a0_3, sAl + aRow * 272 + kb + aColB);
            LDSM_X4(a1_0, a1_1, a1_2, a1_3, sAl + (aRow + 16) * 272 + kb + aColB);
            #pragma unroll
            for (int bb = 0; bb < 4; bb++)
                LDSM_X4(bfr[2*bb][0], bfr[2*bb][1], bfr[2*bb+1][0], bfr[2*bb+1][1],
                        sBh + (bRow + bb * 16) * 272 + kb + bColB);
            #pragma unroll
            for (int nb = 0; nb < 8; nb++) {
                MMA16816(acc[0][nb], a0_0, a0_1, a0_2, a0_3, bfr[nb][0], bfr[nb][1]);
                MMA16816(acc[1][nb], a1_0, a1_1, a1_2, a1_3, bfr[nb][0], bfr[nb][1]);
            }
        }

        // epilogue: add t, store. acc[i][nb]: c0,c1 -> row r0, c2,c3 -> r0+8
        {
            const int rl = lane >> 2;
            const int cl = 2 * (lane & 3);
            #pragma unroll
            for (int i = 0; i < 2; i++) {
                int r0 = mbase + i * 16 + rl;
                int r1 = r0 + 8;
                int mi0 = r0 / 25, w0 = r0 - mi0 * 25;
                int mi1 = r1 / 25, w1 = r1 - mi1 * 25;
                #pragma unroll
                for (int nb = 0; nb < 8; nb++) {
                    int col = nbase + nb * 8 + cl;
                    if (r0 < 125) {
                        float2 o2;
                        o2.x = acc[i][nb][0] + t_s[mi0 * 128 + col];
                        o2.y = acc[i][nb][1] + t_s[mi0 * 128 + col + 1];
                        *(float2*)&out[(size_t)(tile * 5 + mi0) * 3200 + w0 * 128 + col] = o2;
                    }
                    if (r1 < 125) {
                        float2 o2;
                        o2.x = acc[i][nb][2] + t_s[mi1 * 128 + col];
                        o2.y = acc[i][nb][3] + t_s[mi1 * 128 + col + 1];
                        *(float2*)&out[(size_t)(tile * 5 + mi1) * 3200 + w1 * 128 + col] = o2;
                    }
                }
            }
        }
        __syncthreads();   // t_s / A reused next tile
    }
}

// ---------------------------------------------------------------------------
extern "C" void kernel_launch(void* const* d_in, const int* in_sizes, int n_in,
                              void* d_out, int out_size)
{
    (void)in_sizes; (void)n_in; (void)out_size;
    const float* feat_f0 = (const float*)d_in[0];
    const float* feat_f1 = (const float*)d_in[1];
    const float* feat_c0 = (const float*)d_in[2];
    const float* feat_c1 = (const float*)d_in[3];
    const int*   b_ids   = (const int*)d_in[4];
    const int*   i_ids   = (const int*)d_in[5];
    const int*   j_ids   = (const int*)d_in[6];
    const float* Wd      = (const float*)d_in[7];
    const float* bd      = (const float*)d_in[8];
    const float* Wm      = (const float*)d_in[9];
    const float* bm      = (const float*)d_in[10];
    float* out = (float*)d_out;

    const size_t smemW = (128 * 129 + 16 * 132) * sizeof(float);
    const size_t smemP = 16384 + 32768 + 64 * sizeof(float*);
    const size_t smemF = 4 * (size_t)ABYTES + 2560 + 96;   // ~142 KB

    cudaFuncSetAttribute(wc_kernel,   cudaFuncAttributeMaxDynamicSharedMemorySize, (int)smemW);
    cudaFuncSetAttribute(proj_kernel, cudaFuncAttributeMaxDynamicSharedMemorySize, (int)smemP);
    cudaFuncSetAttribute(fine_kernel, cudaFuncAttributeMaxDynamicSharedMemorySize, (int)smemF);

    wc_kernel<<<16, 256, smemW>>>(Wd, bd, Wm, bm);
    proj_kernel<<<157, 256, smemP>>>(feat_c0, feat_c1, b_ids, i_ids, j_ids);
    fine_kernel<<<148, 256, smemF>>>(feat_f0, feat_f1, b_ids, i_ids, j_ids, Wm, out);
}